// round 17
// baseline (speedup 1.0000x reference)
#include <cuda_runtime.h>
#include <cuda_fp16.h>
#include <stdint.h>

// ---------------- problem constants ----------------
#define BATCH 16
#define SEQ   4096
#define FEAT  512
#define MROWS (BATCH*SEQ)          // 65536
#define M_CTA 64
#define NUM_CTAS (MROWS/M_CTA)     // 1024
#define THREADS 256
#define NKT 16                     // K slices of 32
#define NCH 4                      // N chunks of 128

#define A_BYTES   65536            // 64 rows x 512 f16 (1024B/row, XOR-swizzled)

// smem layout (bytes)
#define OFF_U    0                 // 2048
#define OFF_BV   2048              // 2048
#define OFF_SRED 4096              // 4*64 floats = 1024
#define OFF_SE   5120              // 64 floats = 256
#define OFF_A    5376              // 65536
#define SMEM_TOTAL (OFF_A + A_BYTES)   // 70912 (x3 CTAs = 212736 < 228KB)

// ---------------- global scratch ----------------
__device__ uint4  g_Wfrag[32768];              // f16 fragment-major W (512 KB)
__device__ float  g_part[NUM_CTAS];
__device__ float  g_po[(size_t)NUM_CTAS*FEAT];

__device__ __forceinline__ uint32_t pack_f16x2(float lo, float hi) {
    __half2 h = __floats2half2_rn(lo, hi);
    return *(uint32_t*)&h;
}

__device__ __forceinline__ void mma_f16(float& d0, float& d1, float& d2, float& d3,
                                        uint32_t a0, uint32_t a1, uint32_t a2, uint32_t a3,
                                        uint32_t b0, uint32_t b1) {
    asm volatile(
        "mma.sync.aligned.m16n8k16.row.col.f32.f16.f16.f32 "
        "{%0,%1,%2,%3}, {%4,%5,%6,%7}, {%8,%9}, {%0,%1,%2,%3};"
        : "+f"(d0), "+f"(d1), "+f"(d2), "+f"(d3)
        : "r"(a0), "r"(a1), "r"(a2), "r"(a3), "r"(b0), "r"(b1));
}

__device__ __forceinline__ void ldsm_x4(uint32_t& r0, uint32_t& r1, uint32_t& r2, uint32_t& r3,
                                        uint32_t addr) {
    asm volatile("ldmatrix.sync.aligned.m8n8.x4.shared.b16 {%0,%1,%2,%3}, [%4];"
                 : "=r"(r0), "=r"(r1), "=r"(r2), "=r"(r3) : "r"(addr));
}

__device__ __forceinline__ uint32_t smem_u32(const void* p) {
    uint32_t a;
    asm("{ .reg .u64 t; cvta.to.shared.u64 t, %1; cvt.u32.u64 %0, t; }" : "=r"(a) : "l"(p));
    return a;
}

// fast tanh via 2 MUFU; rel err ~1e-6, saturates to +-1
__device__ __forceinline__ float ftanh(float v) {
    float t = __expf(2.0f * v);
    return 1.0f - __fdividef(2.0f, t + 1.0f);
}

// ---------------- k0: pack W -> f16 fragment-major (R13-measured variant) ----------------
__global__ void k0_pack(const float* __restrict__ W) {
    int g = blockIdx.x * 256 + threadIdx.x;          // 0..32767
    int lane = g & 31;
    int t    = g >> 5;
    int ntp  = t & 3;
    int wn   = (t >> 2) & 3;
    int ks   = (t >> 4) & 1;
    int nc   = (t >> 5) & 1;
    int kt   = t >> 6;
    int k   = kt * 32 + ks * 16 + 2 * (lane & 3);
    int np0 = nc * 256 + wn * 64 + ntp * 16 + (lane >> 2);
    int np1 = np0 + 8;
    uint4 v;
    v.x = pack_f16x2(W[(size_t)k * FEAT + np0],       W[(size_t)(k + 1) * FEAT + np0]);
    v.y = pack_f16x2(W[(size_t)(k + 8) * FEAT + np0], W[(size_t)(k + 9) * FEAT + np0]);
    v.z = pack_f16x2(W[(size_t)k * FEAT + np1],       W[(size_t)(k + 1) * FEAT + np1]);
    v.w = pack_f16x2(W[(size_t)(k + 8) * FEAT + np1], W[(size_t)(k + 9) * FEAT + np1]);
    g_Wfrag[g] = v;
    // allow dependent k1 grids to launch as soon as stores are issued
    cudaTriggerProgrammaticLaunchCompletion();
}

// B fragment gather for (global-iter git, warp wn, lane): 4 uint4
// git = c*16 + kt; chunk c covers cols [c*128, +128); warp covers 32 cols.
// Maps onto packed layout via wno=(c&1)*2+(wn>>1), ntpo=(wn&1)*2+ntp.
__device__ __forceinline__ void ldg_B(uint4 bb[4], int git, int wn, int lane) {
    const int c = git >> 4, kt = git & 15;
    const uint4* __restrict__ slab = g_Wfrag + (size_t)(kt * 2 + (c >> 1)) * 1024;
    const int base = ((c & 1) * 2 + (wn >> 1)) * 4 + (wn & 1) * 2;
    #pragma unroll
    for (int ks = 0; ks < 2; ks++)
        #pragma unroll
        for (int ntp = 0; ntp < 2; ntp++)
            bb[ks * 2 + ntp] = __ldg(slab + (size_t)((ks * 16 + base + ntp) * 32 + lane));
}

// ---------------- k1: A-resident, barrier-free K-loop, occupancy 3, PDL ----------------
__global__ __launch_bounds__(THREADS, 3)
void k1_gemm(const float* __restrict__ xg, const float* __restrict__ bg,
             const float* __restrict__ ug) {
    extern __shared__ char smem[];
    const uint32_t sbase = smem_u32(smem);
    const int tid  = threadIdx.x;
    const int lane = tid & 31;
    const int wid  = tid >> 5;
    const int wm   = wid & 1;        // 2 row groups of 32
    const int wn   = wid >> 1;       // 4 col groups of 32 (within 128-chunk)
    const int lr   = lane >> 2;
    const int lc   = lane & 3;
    const int row0 = blockIdx.x * M_CTA;

    float* usm  = (float*)(smem + OFF_U);
    float* bsm  = (float*)(smem + OFF_BV);
    float* sred = (float*)(smem + OFF_SRED);
    float* se_s = (float*)(smem + OFF_SE);

    #pragma unroll
    for (int i = 0; i < 2; i++) {
        usm[tid + i * THREADS] = ug[tid + i * THREADS];
        bsm[tid + i * THREADS] = bg[tid + i * THREADS];
    }

    // ---- A prologue (independent of k0): load x-tile, convert to f16 smem ----
    {
        uint32_t* As = (uint32_t*)(smem + OFF_A);
        #pragma unroll
        for (int i = 0; i < 32; i++) {
            int id = tid + i * THREADS;       // float4 index, 0..8191
            int r  = id >> 7;
            int c4 = id & 127;
            float4 v = *(const float4*)(xg + (size_t)(row0 + r) * FEAT + c4 * 4);
            int w0 = c4 * 2;
            int sw = w0 ^ ((r & 7) << 2);
            As[r * 256 + sw]     = pack_f16x2(v.x, v.y);
            As[r * 256 + sw + 1] = pack_f16x2(v.z, v.w);
        }
    }
    __syncthreads();        // A visible; K-loop below is barrier-free

    // wait for k0's g_Wfrag before any B read (PDL dependency)
    cudaGridDependencySynchronize();

    // ldmatrix per-lane address components
    const int j    = lane >> 3;
    const int rj   = lane & 7;
    const int rowj = wm * 32 + (j & 1) * 8 + rj;
    const int cj   = (j >> 1) * 4;
    const int sj   = rj << 2;
    const uint32_t A0 = sbase + OFF_A;

    float sp[2][2] = {{0.f, 0.f}, {0.f, 0.f}};
    const uint32_t* As = (const uint32_t*)(smem + OFF_A);

    for (int c = 0; c < NCH; c++) {
        float acc[2][4][4];
        #pragma unroll
        for (int mt = 0; mt < 2; mt++)
            #pragma unroll
            for (int nt = 0; nt < 4; nt++)
                acc[mt][nt][0] = acc[mt][nt][1] = acc[mt][nt][2] = acc[mt][nt][3] = 0.0f;

        #pragma unroll
        for (int kt = 0; kt < NKT; kt++) {
            const int git = c * NKT + kt;
            uint4 bb[4];
            ldg_B(bb, git, wn, lane);

            const uint32_t wordbase = rowj * 256 + (((kt * 16) | cj) ^ sj);
            #pragma unroll
            for (int ks = 0; ks < 2; ks++) {
                const uint32_t wks = wordbase ^ (ks << 3);
                uint32_t a[2][4];
                #pragma unroll
                for (int mt = 0; mt < 2; mt++)
                    ldsm_x4(a[mt][0], a[mt][1], a[mt][2], a[mt][3],
                            A0 + mt * 16384 + (wks << 2));
                #pragma unroll
                for (int ntp = 0; ntp < 2; ntp++) {
                    uint4 b4 = bb[ks * 2 + ntp];
                    #pragma unroll
                    for (int mt = 0; mt < 2; mt++) {
                        mma_f16(acc[mt][2*ntp][0], acc[mt][2*ntp][1],
                                acc[mt][2*ntp][2], acc[mt][2*ntp][3],
                                a[mt][0], a[mt][1], a[mt][2], a[mt][3], b4.x, b4.y);
                        mma_f16(acc[mt][2*ntp+1][0], acc[mt][2*ntp+1][1],
                                acc[mt][2*ntp+1][2], acc[mt][2*ntp+1][3],
                                a[mt][0], a[mt][1], a[mt][2], a[mt][3], b4.z, b4.w);
                    }
                }
            }
        }

        // epilogue for this 128-chunk: tanh + dot(u), fixed order
        #pragma unroll
        for (int mt = 0; mt < 2; mt++) {
            #pragma unroll
            for (int nt = 0; nt < 4; nt++) {
                int n = c * 128 + wn * 32 + nt * 8 + lc * 2;
                float u0 = usm[n], u1 = usm[n + 1];
                float b0 = bsm[n], b1 = bsm[n + 1];
                sp[mt][0] += ftanh(acc[mt][nt][0] + b0) * u0;
                sp[mt][0] += ftanh(acc[mt][nt][1] + b1) * u1;
                sp[mt][1] += ftanh(acc[mt][nt][2] + b0) * u0;
                sp[mt][1] += ftanh(acc[mt][nt][3] + b1) * u1;
            }
        }
    }

    // reduce over 4 lanes sharing a row (fixed order)
    #pragma unroll
    for (int mt = 0; mt < 2; mt++) {
        #pragma unroll
        for (int h = 0; h < 2; h++) {
            sp[mt][h] += __shfl_xor_sync(0xffffffffu, sp[mt][h], 1);
            sp[mt][h] += __shfl_xor_sync(0xffffffffu, sp[mt][h], 2);
        }
    }
    __syncthreads();
    if ((lane & 3) == 0) {
        #pragma unroll
        for (int mt = 0; mt < 2; mt++) {
            int r = wm * 32 + mt * 16 + lr;
            sred[wn * 64 + r]     = sp[mt][0];
            sred[wn * 64 + r + 8] = sp[mt][1];
        }
    }
    __syncthreads();

    if (tid < M_CTA) {
        float s = (sred[tid] + sred[64 + tid]) + (sred[128 + tid] + sred[192 + tid]);
        float e = expf(s);
        se_s[tid] = e;
        sred[tid] = e;
    }
    __syncthreads();
    #pragma unroll
    for (int off = 32; off > 0; off >>= 1) {
        if (tid < off) sred[tid] += sred[tid + off];
        __syncthreads();
    }
    if (tid == 0) g_part[blockIdx.x] = sred[0];

    // pooling partial from f16 A smem
    {
        float p0 = 0.f, p1 = 0.f;
        #pragma unroll 4
        for (int r = 0; r < M_CTA; r++) {
            uint32_t hw = As[r * 256 + (tid ^ ((r & 7) << 2))];
            float2 xf = __half22float2(*(__half2*)&hw);
            float ev = se_s[r];
            p0 += xf.x * ev;
            p1 += xf.y * ev;
        }
        float2* po = (float2*)(g_po + (size_t)blockIdx.x * FEAT);
        po[tid] = make_float2(p0, p1);
    }
}

// ---------------- k4: global-sum + combine + normalize (PDL after k1) ----------------
__global__ __launch_bounds__(128)
void k4_final(float* __restrict__ out) {
    __shared__ float red[128];
    __shared__ float pos[128];
    const int tid = threadIdx.x;
    const int b = blockIdx.y, q = blockIdx.x;   // q 0..15

    cudaGridDependencySynchronize();   // g_part / g_po ready

    float v = 0.0f;
    #pragma unroll
    for (int i = 0; i < 8; i++)
        v += g_part[tid * 8 + i];
    red[tid] = v;
    __syncthreads();
    #pragma unroll
    for (int off = 64; off > 0; off >>= 1) {
        if (tid < off) red[tid] += red[tid + off];
        __syncthreads();
    }
    const float denom = red[0] + 1e-7f;

    const int ft = tid >> 2, ci = tid & 3;
    const int f = q * 32 + ft;
    float s = 0.0f;
    #pragma unroll
    for (int i = 0; i < 16; i++) {
        int c = ci * 16 + i;
        s += g_po[(size_t)(b * 64 + c) * FEAT + f];
    }
    pos[tid] = s;
    __syncthreads();
    if (ci == 0) {
        float tot = ((pos[tid] + pos[tid + 1]) + pos[tid + 2]) + pos[tid + 3];
        out[b * FEAT + f] = tot / denom;
    }
}

extern "C" void kernel_launch(void* const* d_in, const int* in_sizes, int n_in,
                              void* d_out, int out_size) {
    const float* x = (const float*)d_in[0];
    const float* W = (const float*)d_in[1];
    const float* b = (const float*)d_in[2];
    const float* u = (const float*)d_in[3];
    float* out = (float*)d_out;

    cudaFuncSetAttribute(k1_gemm, cudaFuncAttributeMaxDynamicSharedMemorySize, SMEM_TOTAL);

    k0_pack<<<128, 256>>>(W);

    // k1 with programmatic dependent launch (overlaps its A prologue with k0)
    {
        cudaLaunchConfig_t cfg = {};
        cudaLaunchAttribute attr[1];
        attr[0].id = cudaLaunchAttributeProgrammaticStreamSerialization;
        attr[0].val.programmaticStreamSerializationAllowed = 1;
        cfg.gridDim = dim3(NUM_CTAS);
        cfg.blockDim = dim3(THREADS);
        cfg.dynamicSmemBytes = SMEM_TOTAL;
        cfg.stream = 0;
        cfg.attrs = attr;
        cfg.numAttrs = 1;
        cudaLaunchKernelEx(&cfg, k1_gemm, x, b, u);
    }

    // k4 with PDL (hides launch latency behind k1 tail)
    {
        cudaLaunchConfig_t cfg = {};
        cudaLaunchAttribute attr[1];
        attr[0].id = cudaLaunchAttributeProgrammaticStreamSerialization;
        attr[0].val.programmaticStreamSerializationAllowed = 1;
        cfg.gridDim = dim3(16, BATCH);
        cfg.blockDim = dim3(128);
        cfg.dynamicSmemBytes = 0;
        cfg.stream = 0;
        cfg.attrs = attr;
        cfg.numAttrs = 1;
        cudaLaunchKernelEx(&cfg, k4_final, out);
    }
}